// round 8
// baseline (speedup 1.0000x reference)
#include <cuda_runtime.h>
#include <cstdint>
#include <cstddef>

// ---------------------------------------------------------------------------
// Problem dims
// ---------------------------------------------------------------------------
static constexpr int Mdim = 8192;    // B*S
static constexpr int Kdim = 4096;    // in features
static constexpr int Ndim = 16384;   // out features

// GEMM tiling: 2 CTAs/SM, each 64(M) x 128(N), 8 warps (2m x 4n), warp 32x32
static constexpr int MT = 64;
static constexpr int NT = 128;
static constexpr int KT = 64;                 // int8 k per chunk (64B rows)
static constexpr int CHUNKS = Kdim / KT;      // 64
static constexpr int STAGES = 6;              // 3 pairs in flight
static constexpr int NTILES = (Mdim / MT) * (Ndim / NT);    // 16384
static constexpr int NTHREADS = 256;
static constexpr int A_BYTES = 64 * 64;       // 4KB per A tile (hi or lo)
static constexpr int B_BYTES = 128 * 64;      // 8KB
static constexpr int STAGE_BYTES = 2 * A_BYTES + B_BYTES;   // 16KB
static constexpr int SMEM_TOTAL  = STAGES * STAGE_BYTES + 128;  // 96KB + slot

// Quantization: X = round(4096 * x), X = 256*h + l
static constexpr float QSCALE = 4096.0f;

// ---------------------------------------------------------------------------
// Scratch (static device allocations; no runtime alloc)
// ---------------------------------------------------------------------------
__device__ __align__(128) char  g_hi[(size_t)Mdim * Kdim];   // 32MB
__device__ __align__(128) char  g_lo[(size_t)Mdim * Kdim];   // 32MB
__device__ __align__(128) char  g_w8[(size_t)Ndim * Kdim];   // 64MB
__device__ __align__(128) float g_rcp[Ndim];
__device__ unsigned int g_ctr;

// ---------------------------------------------------------------------------
// Helpers
// ---------------------------------------------------------------------------
__device__ __forceinline__ uint32_t smem_u32(const void* p) {
    uint32_t a;
    asm("{ .reg .u64 t; cvta.to.shared.u64 t, %1; cvt.u32.u64 %0, t; }" : "=r"(a) : "l"(p));
    return a;
}
__device__ __forceinline__ void lds64(uint32_t& x, uint32_t& y, uint32_t addr) {
    asm volatile("ld.shared.v2.u32 {%0, %1}, [%2];" : "=r"(x), "=r"(y) : "r"(addr));
}
__device__ __forceinline__ void imma16832(int* c, const uint32_t* a, const uint32_t* b) {
    asm volatile(
        "mma.sync.aligned.m16n8k32.row.col.s32.s8.s8.s32 "
        "{%0,%1,%2,%3}, {%4,%5,%6,%7}, {%8,%9}, {%0,%1,%2,%3};"
        : "+r"(c[0]), "+r"(c[1]), "+r"(c[2]), "+r"(c[3])
        : "r"(a[0]), "r"(a[1]), "r"(a[2]), "r"(a[3]), "r"(b[0]), "r"(b[1]));
}
__device__ __forceinline__ void cp16(uint32_t dst, uint64_t gsrc) {
    asm volatile("cp.async.cg.shared.global [%0], [%1], 16;" :: "r"(dst), "l"(gsrc) : "memory");
}
__device__ __forceinline__ int quant(float v) {
    float s = v * QSCALE;
    s = fminf(fmaxf(s, -32768.0f), 32639.0f);
    return __float2int_rn(s);
}
__device__ __forceinline__ uint32_t pack4(int b0, int b1, int b2, int b3) {
    return (uint32_t)(b0 & 255) | ((uint32_t)(b1 & 255) << 8) |
           ((uint32_t)(b2 & 255) << 16) | ((uint32_t)(b3 & 255) << 24);
}

// ---------------------------------------------------------------------------
// Preprocess: x fp32 -> (hi, lo) int8, K-pair-permuted layout.
// ---------------------------------------------------------------------------
__global__ void convert_x_kernel(const float4* __restrict__ x,
                                 uint2* __restrict__ hi, uint2* __restrict__ lo) {
    int id = blockIdx.x * blockDim.x + threadIdx.x;       // 0 .. M*K/8-1
    int t = id & 3, g = (id >> 2) & 127, row = id >> 9;
    int f4 = row * 1024 + g * 8 + t;                      // float4 index of cols 4t..4t+3
    float4 a = x[f4];
    float4 b = x[f4 + 4];                                 // cols 16+4t..19+4t
    int Xa0 = quant(a.x), Xa1 = quant(a.y), Xa2 = quant(a.z), Xa3 = quant(a.w);
    int Xb0 = quant(b.x), Xb1 = quant(b.y), Xb2 = quant(b.z), Xb3 = quant(b.w);
    int ha0 = (Xa0 + 128) >> 8, ha1 = (Xa1 + 128) >> 8, ha2 = (Xa2 + 128) >> 8, ha3 = (Xa3 + 128) >> 8;
    int hb0 = (Xb0 + 128) >> 8, hb1 = (Xb1 + 128) >> 8, hb2 = (Xb2 + 128) >> 8, hb3 = (Xb3 + 128) >> 8;
    uint2 hv, lv;
    hv.x = pack4(ha0, ha1, ha2, ha3);
    hv.y = pack4(hb0, hb1, hb2, hb3);
    lv.x = pack4(Xa0 - (ha0 << 8), Xa1 - (ha1 << 8), Xa2 - (ha2 << 8), Xa3 - (ha3 << 8));
    lv.y = pack4(Xb0 - (hb0 << 8), Xb1 - (hb1 << 8), Xb2 - (hb2 << 8), Xb3 - (hb3 << 8));
    int o = row * 512 + g * 4 + t;
    hi[o] = hv;
    lo[o] = lv;
}

// convert_w also computes rcp[] and resets the work counter (saves a launch)
__global__ void convert_w_kernel(const int4* __restrict__ w, uint2* __restrict__ w8,
                                 const float* __restrict__ scales, float* __restrict__ rcp) {
    int id = blockIdx.x * blockDim.x + threadIdx.x;       // 0 .. N*K/8-1
    int t = id & 3, g = (id >> 2) & 127, row = id >> 9;
    int i4 = row * 1024 + g * 8 + t;
    int4 a = w[i4];
    int4 b = w[i4 + 4];
    uint2 v;
    v.x = pack4(a.x, a.y, a.z, a.w);
    v.y = pack4(b.x, b.y, b.z, b.w);
    w8[row * 512 + g * 4 + t] = v;
    if (id < Ndim) rcp[id] = 1.0f / (QSCALE * scales[id]);
    if (id == 0) g_ctr = 0;   // reset persistent-kernel work counter each replay
}

// ---------------------------------------------------------------------------
// Main GEMM: 2 CTAs/SM (independent barriers cover each other's bubbles),
// persistent work-stealing, continuous cp.async pipeline across tiles,
// paired chunks: one __syncthreads per 2 chunks (STAGES=6: 3 pairs in flight).
// int8 IMMA, hi/lo accumulated separately in s32.
// ---------------------------------------------------------------------------
__global__ void __launch_bounds__(NTHREADS, 2)
a16w8_imma_kernel(const char* __restrict__ gHi, const char* __restrict__ gLo,
                  const char* __restrict__ gW, const float* __restrict__ rcp,
                  const float* __restrict__ bias, float* __restrict__ out) {
    extern __shared__ __align__(128) char smem[];
    const uint32_t sbase = smem_u32(smem);
    unsigned* slot = (unsigned*)(smem + STAGES * STAGE_BYTES);
    const int tid  = threadIdx.x;
    const int lane = tid & 31;
    const int wid  = tid >> 5;
    const int g = lane >> 2, t = lane & 3;
    const int wm = wid >> 2, wn = wid & 3;          // warp grid 2 (m) x 4 (n)

    // --- per-thread load decomposition (fixed across tiles): 4 x 16B/stage ---
    int      psel[4];        // 0: A-hi, 1: A-lo, 2: B
    uint64_t prow[4];        // rowLocal*Kdim + c*16
    uint32_t dsto[4];
    #pragma unroll
    for (int p = 0; p < 4; p++) {
        int idx = tid + p * NTHREADS;
        int sel = (idx < 256) ? 0 : (idx < 512 ? 1 : 2);
        int row = (sel == 2) ? ((idx - 512) >> 2) : ((idx & 255) >> 2);
        int c   = idx & 3;
        psel[p] = sel;
        prow[p] = (uint64_t)row * Kdim + (uint64_t)c * 16;
        dsto[p] = sel * A_BYTES + row * 64 + ((c ^ (row & 3)) * 16);
    }
    uint64_t baseHi, baseLo, baseW;
    asm("cvta.to.global.u64 %0, %1;" : "=l"(baseHi) : "l"(gHi));
    asm("cvta.to.global.u64 %0, %1;" : "=l"(baseLo) : "l"(gLo));
    asm("cvta.to.global.u64 %0, %1;" : "=l"(baseW)  : "l"(gW));

    // --- fragment smem offsets (within a stage) ---
    uint32_t aoff[2], boff[4], cko[2];
    #pragma unroll
    for (int i = 0; i < 2; i++) aoff[i] = (wm * 32 + g + 16 * i) * 64;
    #pragma unroll
    for (int j = 0; j < 4; j++) boff[j] = 2 * A_BYTES + (wn * 32 + j * 8 + g) * 64;
    #pragma unroll
    for (int ks = 0; ks < 2; ks++)
        cko[ks] = (((ks * 2 + (t >> 1)) ^ (g & 3)) * 16) + (t & 1) * 8;

    // --- steal first tile ---
    if (tid == 0) slot[0] = atomicAdd(&g_ctr, 1u);
    __syncthreads();
    unsigned cur = slot[0];
    if (cur >= NTILES) return;

    // strip raster: 16 m-tiles per strip, sweep all 128 n-tiles
    int m0 = (int)(((cur & 15) | ((cur >> 11) << 4)) * MT);
    int n0 = (int)(((cur >> 4) & 127) * NT);

    uint64_t srcC[4], srcN[4];
    #pragma unroll
    for (int p = 0; p < 4; p++) {
        int r0 = (psel[p] == 2) ? n0 : m0;
        uint64_t b = (psel[p] == 0) ? baseHi : (psel[p] == 1) ? baseLo : baseW;
        srcC[p] = b + (uint64_t)r0 * Kdim + prow[p];
    }

    // --- prologue: fill stages 0..3 (chunks 0..3) as two 2-stage groups ---
    #pragma unroll
    for (int grp = 0; grp < 2; grp++) {
        #pragma unroll
        for (int h = 0; h < 2; h++) {
            int s = grp * 2 + h;
            uint32_t sb = sbase + s * STAGE_BYTES;
            #pragma unroll
            for (int p = 0; p < 4; p++) cp16(sb + dsto[p], srcC[p] + (uint64_t)s * KT);
        }
        asm volatile("cp.async.commit_group;" ::: "memory");
    }

    int sread = 0, sfill = 4;

    // --- persistent tile loop ---
    for (;;) {
        // steal next tile (one ahead, enables cross-tile prefetch)
        if (tid == 0) slot[0] = atomicAdd(&g_ctr, 1u);
        __syncthreads();
        const unsigned nxt = slot[0];
        const bool have_next = (nxt < NTILES);
        int nm0 = 0, nn0 = 0;
        if (have_next) {
            nm0 = (int)(((nxt & 15) | ((nxt >> 11) << 4)) * MT);
            nn0 = (int)(((nxt >> 4) & 127) * NT);
            #pragma unroll
            for (int p = 0; p < 4; p++) {
                int r0 = (psel[p] == 2) ? nn0 : nm0;
                uint64_t b = (psel[p] == 0) ? baseHi : (psel[p] == 1) ? baseLo : baseW;
                srcN[p] = b + (uint64_t)r0 * Kdim + prow[p];
            }
        }

        // accumulators: warp tile 32x32 -> 2(m16) x 4(n8) x 4 regs, hi+lo
        int ch[2][4][4], cl[2][4][4];
        #pragma unroll
        for (int i = 0; i < 2; i++)
            #pragma unroll
            for (int j = 0; j < 4; j++)
                #pragma unroll
                for (int r = 0; r < 4; r++) { ch[i][j][r] = 0; cl[i][j][r] = 0; }

        // --- chunk-pair loop (one sync + one commit per 2 chunks) ---
        #pragma unroll 1
        for (int p2 = 0; p2 < CHUNKS / 2; p2++) {
            asm volatile("cp.async.wait_group 1;" ::: "memory");
            __syncthreads();

            // refill pair p2+2 (chunks 2*p2+4, 2*p2+5), one commit group
            {
                const int c0 = 2 * p2 + 4;
                #pragma unroll
                for (int h = 0; h < 2; h++) {
                    int sf = sfill + h; if (sf >= STAGES) sf -= STAGES;
                    const uint32_t sb = sbase + sf * STAGE_BYTES;
                    const int fc = c0 + h;
                    if (fc < CHUNKS) {
                        const uint64_t ko = (uint64_t)fc * KT;
                        #pragma unroll
                        for (int p = 0; p < 4; p++) cp16(sb + dsto[p], srcC[p] + ko);
                    } else if (have_next) {
                        const uint64_t ko = (uint64_t)(fc - CHUNKS) * KT;
                        #pragma unroll
                        for (int p = 0; p < 4; p++) cp16(sb + dsto[p], srcN[p] + ko);
                    }
                }
                asm volatile("cp.async.commit_group;" ::: "memory");
                sfill += 2; if (sfill >= STAGES) sfill -= STAGES;
            }

            // compute the two ready chunks
            #pragma unroll
            for (int h = 0; h < 2; h++) {
                int sr = sread + h; if (sr >= STAGES) sr -= STAGES;
                const uint32_t st = sbase + sr * STAGE_BYTES;
                #pragma unroll
                for (int ks = 0; ks < 2; ks++) {
                    uint32_t ah[2][4], al[2][4], bb[4][2];
                    #pragma unroll
                    for (int i = 0; i < 2; i++) {
                        uint32_t a = st + aoff[i] + cko[ks];
                        lds64(ah[i][0], ah[i][2], a);
                        lds64(ah[i][1], ah[i][3], a + 8 * 64);
                        lds64(al[i][0], al[i][2], a + A_BYTES);
                        lds64(al[i][1], al[i][3], a + A_BYTES + 8 * 64);
                    }
                    #pragma unroll
                    for (int j = 0; j < 4; j++)
                        lds64(bb[j][0], bb[j][1], st + boff[j] + cko[ks]);
                    #pragma unroll
                    for (int i = 0; i < 2; i++)
                        #pragma unroll
                        for (int j = 0; j < 4; j++) {
                            imma16832(ch[i][j], ah[i], bb[j]);
                            imma16832(cl[i][j], al[i], bb[j]);
                        }
                }
            }
            sread += 2; if (sread >= STAGES) sread -= STAGES;
        }

        // --- epilogue (next tile's first chunks already in flight) ---
        #pragma unroll
        for (int i = 0; i < 2; i++) {
            const int r0 = m0 + wm * 32 + i * 16 + g;
            #pragma unroll
            for (int j = 0; j < 4; j++) {
                const int c = n0 + wn * 32 + j * 8 + t * 2;
                const float rs0 = __ldg(rcp + c), rs1 = __ldg(rcp + c + 1);
                const float b0  = __ldg(bias + c), b1 = __ldg(bias + c + 1);
                float v0 = fmaf(256.0f, (float)ch[i][j][0], (float)cl[i][j][0]);
                float v1 = fmaf(256.0f, (float)ch[i][j][1], (float)cl[i][j][1]);
                float v2 = fmaf(256.0f, (float)ch[i][j][2], (float)cl[i][j][2]);
                float v3 = fmaf(256.0f, (float)ch[i][j][3], (float)cl[i][j][3]);
                float2 o0; o0.x = v0 * rs0 + b0; o0.y = v1 * rs1 + b1;
                float2 o1; o1.x = v2 * rs0 + b0; o1.y = v3 * rs1 + b1;
                *(float2*)(out + (size_t)r0 * Ndim + c)       = o0;
                *(float2*)(out + (size_t)(r0 + 8) * Ndim + c) = o1;
            }
        }

        if (!have_next) break;
        m0 = nm0; n0 = nn0;
        #pragma unroll
        for (int p = 0; p < 4; p++) srcC[p] = srcN[p];
    }
}

// ---------------------------------------------------------------------------
// Host launch
// ---------------------------------------------------------------------------
extern "C" void kernel_launch(void* const* d_in, const int* in_sizes, int n_in,
                              void* d_out, int out_size) {
    const float* x      = (const float*)d_in[0];
    const int*   W_q    = (const int*)d_in[1];
    const float* scales = (const float*)d_in[2];
    const float* bias   = (const float*)d_in[3];
    float*       out    = (float*)d_out;
    (void)in_sizes; (void)n_in; (void)out_size;

    void *pHi = nullptr, *pLo = nullptr, *pW = nullptr, *pRcp = nullptr;
    cudaGetSymbolAddress(&pHi, g_hi);
    cudaGetSymbolAddress(&pLo, g_lo);
    cudaGetSymbolAddress(&pW, g_w8);
    cudaGetSymbolAddress(&pRcp, g_rcp);

    convert_x_kernel<<<(Mdim * (Kdim / 8)) / 256, 256>>>(
        (const float4*)x, (uint2*)pHi, (uint2*)pLo);
    convert_w_kernel<<<(Ndim * (Kdim / 8)) / 256, 256>>>(
        (const int4*)W_q, (uint2*)pW, scales, (float*)pRcp);

    cudaFuncSetAttribute(a16w8_imma_kernel,
                         cudaFuncAttributeMaxDynamicSharedMemorySize, SMEM_TOTAL);

    int nsm = 148;
    cudaDeviceGetAttribute(&nsm, cudaDevAttrMultiProcessorCount, 0);

    a16w8_imma_kernel<<<2 * nsm, NTHREADS, SMEM_TOTAL>>>(
        (const char*)pHi, (const char*)pLo, (const char*)pW,
        (const float*)pRcp, bias, out);
}

// round 9
// speedup vs baseline: 1.0039x; 1.0039x over previous
#include <cuda_runtime.h>
#include <cstdint>
#include <cstddef>

// ---------------------------------------------------------------------------
// Problem dims
// ---------------------------------------------------------------------------
static constexpr int Mdim = 8192;    // B*S
static constexpr int Kdim = 4096;    // in features
static constexpr int Ndim = 16384;   // out features

// GEMM tiling: 2 CTAs/SM, each 64(M) x 128(N), 8 warps (2m x 4n), warp 32x32
static constexpr int MT = 64;
static constexpr int NT = 128;
static constexpr int KT = 64;                 // int8 k per chunk (64B rows)
static constexpr int CHUNKS = Kdim / KT;      // 64
static constexpr int STAGES = 4;
static constexpr int NTILES = (Mdim / MT) * (Ndim / NT);    // 16384
static constexpr int NTHREADS = 256;
static constexpr int A_BYTES = 64 * 64;       // 4KB per A tile (hi or lo)
static constexpr int B_BYTES = 128 * 64;      // 8KB
static constexpr int STAGE_BYTES = 2 * A_BYTES + B_BYTES;   // 16KB
static constexpr int SMEM_TOTAL  = STAGES * STAGE_BYTES + 128;  // 64KB + slot

// Quantization: X = round(4096 * x), X = 256*h + l
static constexpr float QSCALE = 4096.0f;

// Merged convert kernel layout
static constexpr int XBLK = (Mdim * (Kdim / 8)) / 256;      // 16384 blocks for x
static constexpr int WBLK = (Ndim * (Kdim / 8)) / 256;      // 32768 blocks for W

// ---------------------------------------------------------------------------
// Scratch (static device allocations; no runtime alloc)
// ---------------------------------------------------------------------------
__device__ __align__(128) char  g_hi[(size_t)Mdim * Kdim];   // 32MB
__device__ __align__(128) char  g_lo[(size_t)Mdim * Kdim];   // 32MB
__device__ __align__(128) char  g_w8[(size_t)Ndim * Kdim];   // 64MB
__device__ __align__(128) float g_rcp[Ndim];
__device__ unsigned int g_ctr;

// ---------------------------------------------------------------------------
// Helpers
// ---------------------------------------------------------------------------
__device__ __forceinline__ uint32_t smem_u32(const void* p) {
    uint32_t a;
    asm("{ .reg .u64 t; cvta.to.shared.u64 t, %1; cvt.u32.u64 %0, t; }" : "=r"(a) : "l"(p));
    return a;
}
__device__ __forceinline__ void lds64(uint32_t& x, uint32_t& y, uint32_t addr) {
    asm volatile("ld.shared.v2.u32 {%0, %1}, [%2];" : "=r"(x), "=r"(y) : "r"(addr));
}
__device__ __forceinline__ void imma16832(int* c, const uint32_t* a, const uint32_t* b) {
    asm volatile(
        "mma.sync.aligned.m16n8k32.row.col.s32.s8.s8.s32 "
        "{%0,%1,%2,%3}, {%4,%5,%6,%7}, {%8,%9}, {%0,%1,%2,%3};"
        : "+r"(c[0]), "+r"(c[1]), "+r"(c[2]), "+r"(c[3])
        : "r"(a[0]), "r"(a[1]), "r"(a[2]), "r"(a[3]), "r"(b[0]), "r"(b[1]));
}
__device__ __forceinline__ void cp16(uint32_t dst, uint64_t gsrc) {
    asm volatile("cp.async.cg.shared.global [%0], [%1], 16;" :: "r"(dst), "l"(gsrc) : "memory");
}
__device__ __forceinline__ int quant(float v) {
    float s = v * QSCALE;
    s = fminf(fmaxf(s, -32768.0f), 32639.0f);
    return __float2int_rn(s);
}
__device__ __forceinline__ uint32_t pack4(int b0, int b1, int b2, int b3) {
    return (uint32_t)(b0 & 255) | ((uint32_t)(b1 & 255) << 8) |
           ((uint32_t)(b2 & 255) << 16) | ((uint32_t)(b3 & 255) << 24);
}

// ---------------------------------------------------------------------------
// Merged preprocess: one launch covers x-convert, W-convert, rcp, ctr reset.
// K-pair-permuted layout (matches IMMA fragment order).
// ---------------------------------------------------------------------------
__global__ void convert_all_kernel(const float4* __restrict__ x,
                                   const int4* __restrict__ w,
                                   const float* __restrict__ scales,
                                   uint2* __restrict__ hi, uint2* __restrict__ lo,
                                   uint2* __restrict__ w8, float* __restrict__ rcp) {
    if (blockIdx.x < XBLK) {
        int id = blockIdx.x * blockDim.x + threadIdx.x;       // 0 .. M*K/8-1
        int t = id & 3, g = (id >> 2) & 127, row = id >> 9;
        int f4 = row * 1024 + g * 8 + t;
        float4 a = x[f4];
        float4 b = x[f4 + 4];
        int Xa0 = quant(a.x), Xa1 = quant(a.y), Xa2 = quant(a.z), Xa3 = quant(a.w);
        int Xb0 = quant(b.x), Xb1 = quant(b.y), Xb2 = quant(b.z), Xb3 = quant(b.w);
        int ha0 = (Xa0 + 128) >> 8, ha1 = (Xa1 + 128) >> 8;
        int ha2 = (Xa2 + 128) >> 8, ha3 = (Xa3 + 128) >> 8;
        int hb0 = (Xb0 + 128) >> 8, hb1 = (Xb1 + 128) >> 8;
        int hb2 = (Xb2 + 128) >> 8, hb3 = (Xb3 + 128) >> 8;
        uint2 hv, lv;
        hv.x = pack4(ha0, ha1, ha2, ha3);
        hv.y = pack4(hb0, hb1, hb2, hb3);
        lv.x = pack4(Xa0 - (ha0 << 8), Xa1 - (ha1 << 8), Xa2 - (ha2 << 8), Xa3 - (ha3 << 8));
        lv.y = pack4(Xb0 - (hb0 << 8), Xb1 - (hb1 << 8), Xb2 - (hb2 << 8), Xb3 - (hb3 << 8));
        int o = row * 512 + g * 4 + t;
        hi[o] = hv;
        lo[o] = lv;
    } else {
        int id = (blockIdx.x - XBLK) * blockDim.x + threadIdx.x;  // 0 .. N*K/8-1
        int t = id & 3, g = (id >> 2) & 127, row = id >> 9;
        int i4 = row * 1024 + g * 8 + t;
        int4 a = w[i4];
        int4 b = w[i4 + 4];
        uint2 v;
        v.x = pack4(a.x, a.y, a.z, a.w);
        v.y = pack4(b.x, b.y, b.z, b.w);
        w8[row * 512 + g * 4 + t] = v;
        if (id < Ndim) rcp[id] = 1.0f / (QSCALE * scales[id]);
        if (id == 0) g_ctr = 0;   // reset persistent-kernel work counter each replay
    }
}

// ---------------------------------------------------------------------------
// Main GEMM (exact R7 structure): 2 CTAs/SM, persistent work-stealing,
// continuous cp.async pipeline across tiles, per-chunk commit/sync.
// int8 IMMA, hi/lo accumulated separately in s32.
// ---------------------------------------------------------------------------
__global__ void __launch_bounds__(NTHREADS, 2)
a16w8_imma_kernel(const char* __restrict__ gHi, const char* __restrict__ gLo,
                  const char* __restrict__ gW, const float* __restrict__ rcp,
                  const float* __restrict__ bias, float* __restrict__ out) {
    extern __shared__ __align__(128) char smem[];
    const uint32_t sbase = smem_u32(smem);
    unsigned* slot = (unsigned*)(smem + STAGES * STAGE_BYTES);
    const int tid  = threadIdx.x;
    const int lane = tid & 31;
    const int wid  = tid >> 5;
    const int g = lane >> 2, t = lane & 3;
    const int wm = wid >> 2, wn = wid & 3;          // warp grid 2 (m) x 4 (n)

    // --- per-thread load decomposition (fixed across tiles): 4 x 16B/stage ---
    int      psel[4];        // 0: A-hi, 1: A-lo, 2: B
    uint64_t prow[4];        // rowLocal*Kdim + c*16
    uint32_t dsto[4];
    #pragma unroll
    for (int p = 0; p < 4; p++) {
        int idx = tid + p * NTHREADS;
        int sel = (idx < 256) ? 0 : (idx < 512 ? 1 : 2);
        int row = (sel == 2) ? ((idx - 512) >> 2) : ((idx & 255) >> 2);
        int c   = idx & 3;
        psel[p] = sel;
        prow[p] = (uint64_t)row * Kdim + (uint64_t)c * 16;
        dsto[p] = sel * A_BYTES + row * 64 + ((c ^ (row & 3)) * 16);
    }
    uint64_t baseHi, baseLo, baseW;
    asm("cvta.to.global.u64 %0, %1;" : "=l"(baseHi) : "l"(gHi));
    asm("cvta.to.global.u64 %0, %1;" : "=l"(baseLo) : "l"(gLo));
    asm("cvta.to.global.u64 %0, %1;" : "=l"(baseW)  : "l"(gW));

    // --- fragment smem offsets (within a stage) ---
    uint32_t aoff[2], boff[4], cko[2];
    #pragma unroll
    for (int i = 0; i < 2; i++) aoff[i] = (wm * 32 + g + 16 * i) * 64;
    #pragma unroll
    for (int j = 0; j < 4; j++) boff[j] = 2 * A_BYTES + (wn * 32 + j * 8 + g) * 64;
    #pragma unroll
    for (int ks = 0; ks < 2; ks++)
        cko[ks] = (((ks * 2 + (t >> 1)) ^ (g & 3)) * 16) + (t & 1) * 8;

    // --- steal first tile ---
    if (tid == 0) slot[0] = atomicAdd(&g_ctr, 1u);
    __syncthreads();
    unsigned cur = slot[0];
    if (cur >= NTILES) return;

    // strip raster: 16 m-tiles per strip, sweep all 128 n-tiles
    int m0 = (int)(((cur & 15) | ((cur >> 11) << 4)) * MT);
    int n0 = (int)(((cur >> 4) & 127) * NT);

    uint64_t srcC[4], srcN[4];
    #pragma unroll
    for (int p = 0; p < 4; p++) {
        int r0 = (psel[p] == 2) ? n0 : m0;
        uint64_t b = (psel[p] == 0) ? baseHi : (psel[p] == 1) ? baseLo : baseW;
        srcC[p] = b + (uint64_t)r0 * Kdim + prow[p];
    }

    // --- prologue: fill stages 0..2 of first tile, one group per chunk ---
    #pragma unroll
    for (int s = 0; s < STAGES - 1; s++) {
        uint32_t sb = sbase + s * STAGE_BYTES;
        #pragma unroll
        for (int p = 0; p < 4; p++) cp16(sb + dsto[p], srcC[p] + (uint64_t)s * KT);
        asm volatile("cp.async.commit_group;" ::: "memory");
    }

    int sread = 0, sfill = STAGES - 1;

    // --- persistent tile loop ---
    for (;;) {
        // steal next tile (one ahead, enables cross-tile prefetch)
        if (tid == 0) slot[0] = atomicAdd(&g_ctr, 1u);
        __syncthreads();
        const unsigned nxt = slot[0];
        const bool have_next = (nxt < NTILES);
        int nm0 = 0, nn0 = 0;
        if (have_next) {
            nm0 = (int)(((nxt & 15) | ((nxt >> 11) << 4)) * MT);
            nn0 = (int)(((nxt >> 4) & 127) * NT);
            #pragma unroll
            for (int p = 0; p < 4; p++) {
                int r0 = (psel[p] == 2) ? nn0 : nm0;
                uint64_t b = (psel[p] == 0) ? baseHi : (psel[p] == 1) ? baseLo : baseW;
                srcN[p] = b + (uint64_t)r0 * Kdim + prow[p];
            }
        }

        // accumulators: warp tile 32x32 -> 2(m16) x 4(n8) x 4 regs, hi+lo
        int ch[2][4][4], cl[2][4][4];
        #pragma unroll
        for (int i = 0; i < 2; i++)
            #pragma unroll
            for (int j = 0; j < 4; j++)
                #pragma unroll
                for (int r = 0; r < 4; r++) { ch[i][j][r] = 0; cl[i][j][r] = 0; }

        // --- chunk loop (continuous pipeline across tiles) ---
        #pragma unroll 1
        for (int it = 0; it < CHUNKS; it++) {
            asm volatile("cp.async.wait_group %0;" :: "n"(STAGES - 2) : "memory");
            __syncthreads();

            // refill chunk it+3: tail of current tile, or head of next tile
            {
                const int fc = it + STAGES - 1;
                const uint32_t sb = sbase + sfill * STAGE_BYTES;
                if (fc < CHUNKS) {
                    const uint64_t ko = (uint64_t)fc * KT;
                    #pragma unroll
                    for (int p = 0; p < 4; p++) cp16(sb + dsto[p], srcC[p] + ko);
                } else if (have_next) {
                    const uint64_t ko = (uint64_t)(fc - CHUNKS) * KT;
                    #pragma unroll
                    for (int p = 0; p < 4; p++) cp16(sb + dsto[p], srcN[p] + ko);
                }
                asm volatile("cp.async.commit_group;" ::: "memory");
                sfill = (sfill + 1) & (STAGES - 1);
            }

            // compute chunk it
            const uint32_t st = sbase + sread * STAGE_BYTES;
            sread = (sread + 1) & (STAGES - 1);
            #pragma unroll
            for (int ks = 0; ks < 2; ks++) {
                uint32_t ah[2][4], al[2][4], bb[4][2];
                #pragma unroll
                for (int i = 0; i < 2; i++) {
                    uint32_t a = st + aoff[i] + cko[ks];
                    lds64(ah[i][0], ah[i][2], a);
                    lds64(ah[i][1], ah[i][3], a + 8 * 64);
                    lds64(al[i][0], al[i][2], a + A_BYTES);
                    lds64(al[i][1], al[i][3], a + A_BYTES + 8 * 64);
                }
                #pragma unroll
                for (int j = 0; j < 4; j++)
                    lds64(bb[j][0], bb[j][1], st + boff[j] + cko[ks]);
                #pragma unroll
                for (int i = 0; i < 2; i++)
                    #pragma unroll
                    for (int j = 0; j < 4; j++) {
                        imma16832(ch[i][j], ah[i], bb[j]);
                        imma16832(cl[i][j], al[i], bb[j]);
                    }
            }
        }

        // --- epilogue (next tile's first chunks already in flight) ---
        #pragma unroll
        for (int i = 0; i < 2; i++) {
            const int r0 = m0 + wm * 32 + i * 16 + g;
            #pragma unroll
            for (int j = 0; j < 4; j++) {
                const int c = n0 + wn * 32 + j * 8 + t * 2;
                const float rs0 = __ldg(rcp + c), rs1 = __ldg(rcp + c + 1);
                const float b0  = __ldg(bias + c), b1 = __ldg(bias + c + 1);
                float v0 = fmaf(256.0f, (float)ch[i][j][0], (float)cl[i][j][0]);
                float v1 = fmaf(256.0f, (float)ch[i][j][1], (float)cl[i][j][1]);
                float v2 = fmaf(256.0f, (float)ch[i][j][2], (float)cl[i][j][2]);
                float v3 = fmaf(256.0f, (float)ch[i][j][3], (float)cl[i][j][3]);
                float2 o0; o0.x = v0 * rs0 + b0; o0.y = v1 * rs1 + b1;
                float2 o1; o1.x = v2 * rs0 + b0; o1.y = v3 * rs1 + b1;
                *(float2*)(out + (size_t)r0 * Ndim + c)       = o0;
                *(float2*)(out + (size_t)(r0 + 8) * Ndim + c) = o1;
            }
        }

        if (!have_next) break;
        m0 = nm0; n0 = nn0;
        #pragma unroll
        for (int p = 0; p < 4; p++) srcC[p] = srcN[p];
    }
}

// ---------------------------------------------------------------------------
// Host launch
// ---------------------------------------------------------------------------
extern "C" void kernel_launch(void* const* d_in, const int* in_sizes, int n_in,
                              void* d_out, int out_size) {
    const float* x      = (const float*)d_in[0];
    const int*   W_q    = (const int*)d_in[1];
    const float* scales = (const float*)d_in[2];
    const float* bias   = (const float*)d_in[3];
    float*       out    = (float*)d_out;
    (void)in_sizes; (void)n_in; (void)out_size;

    void *pHi = nullptr, *pLo = nullptr, *pW = nullptr, *pRcp = nullptr;
    cudaGetSymbolAddress(&pHi, g_hi);
    cudaGetSymbolAddress(&pLo, g_lo);
    cudaGetSymbolAddress(&pW, g_w8);
    cudaGetSymbolAddress(&pRcp, g_rcp);

    convert_all_kernel<<<XBLK + WBLK, 256>>>(
        (const float4*)x, (const int4*)W_q, scales,
        (uint2*)pHi, (uint2*)pLo, (uint2*)pW, (float*)pRcp);

    cudaFuncSetAttribute(a16w8_imma_kernel,
                         cudaFuncAttributeMaxDynamicSharedMemorySize, SMEM_TOTAL);

    int nsm = 148;
    cudaDeviceGetAttribute(&nsm, cudaDevAttrMultiProcessorCount, 0);

    a16w8_imma_kernel<<<2 * nsm, NTHREADS, SMEM_TOTAL>>>(
        (const char*)pHi, (const char*)pLo, (const char*)pW,
        (const float*)pRcp, bias, out);
}